// round 2
// baseline (speedup 1.0000x reference)
#include <cuda_runtime.h>
#include <cuda_bf16.h>

#define NN 100000
#define NE 400000
#define INF 128
#define HIDF 1024
#define OUTF 64

// scratch (device globals — no allocation allowed)
__device__ float g_deg[NN];
__device__ float g_dinv[NN];
__device__ float g_y[(size_t)NN * INF];      // aggregated x
__device__ float g_h[(size_t)NN * HIDF];     // relu(y@W1+b1)
__device__ float g_z[(size_t)NN * OUTF];     // h@W2

__global__ void init_deg_kernel(float* __restrict__ deg, int n) {
    int i = blockIdx.x * blockDim.x + threadIdx.x;
    if (i < n) deg[i] = 1.0f;  // self-loop weight
}

__global__ void accum_deg_kernel(const int* __restrict__ ei,
                                 const float* __restrict__ ew,
                                 float* __restrict__ deg, int E) {
    int e = blockIdx.x * blockDim.x + threadIdx.x;
    if (e < E) atomicAdd(&deg[ei[E + e]], ew[e]);
}

__global__ void dinv_kernel(const float* __restrict__ deg,
                            float* __restrict__ dinv, int n) {
    int i = blockIdx.x * blockDim.x + threadIdx.x;
    if (i < n) {
        float d = deg[i];
        dinv[i] = d > 0.0f ? rsqrtf(d) : 0.0f;
    }
}

// out[i] = selfnorm(i) * x[i]  (+ bias), vectorized float4
template <int VEC_PER_ROW, bool BIAS>
__global__ void self_init_kernel(const float4* __restrict__ xin,
                                 const float* __restrict__ dinv,
                                 const float4* __restrict__ bias4,
                                 float4* __restrict__ out, int n) {
    int idx = blockIdx.x * blockDim.x + threadIdx.x;
    int total = n * VEC_PER_ROW;
    if (idx >= total) return;
    int i = idx / VEC_PER_ROW;
    int v = idx - i * VEC_PER_ROW;
    float s = dinv[i];
    s = s * s;
    float4 x = xin[idx];
    float4 r;
    r.x = s * x.x; r.y = s * x.y; r.z = s * x.z; r.w = s * x.w;
    if (BIAS) {
        float4 b = bias4[v];
        r.x += b.x; r.y += b.y; r.z += b.z; r.w += b.w;
    }
    out[idx] = r;
}

// one warp per edge: out[dst] += norm * feat[src]
template <int F>
__global__ void scatter_kernel(const int* __restrict__ ei,
                               const float* __restrict__ ew,
                               const float* __restrict__ dinv,
                               const float* __restrict__ feat,
                               float* __restrict__ out, int E) {
    int warp = (blockIdx.x * blockDim.x + threadIdx.x) >> 5;
    int lane = threadIdx.x & 31;
    if (warp >= E) return;
    int s = 0, d = 0;
    float norm = 0.0f;
    if (lane == 0) {
        s = ei[warp];
        d = ei[E + warp];
        norm = dinv[s] * ew[warp] * dinv[d];
    }
    s = __shfl_sync(0xffffffffu, s, 0);
    d = __shfl_sync(0xffffffffu, d, 0);
    norm = __shfl_sync(0xffffffffu, norm, 0);
    if (F == 128) {
        float4 v = reinterpret_cast<const float4*>(feat + (size_t)s * 128)[lane];
        float* o = out + (size_t)d * 128 + lane * 4;
        atomicAdd(o + 0, norm * v.x);
        atomicAdd(o + 1, norm * v.y);
        atomicAdd(o + 2, norm * v.z);
        atomicAdd(o + 3, norm * v.w);
    } else {  // 64
        float2 v = reinterpret_cast<const float2*>(feat + (size_t)s * 64)[lane];
        float* o = out + (size_t)d * 64 + lane * 2;
        atomicAdd(o + 0, norm * v.x);
        atomicAdd(o + 1, norm * v.y);
    }
}

// C[M,N] = A[M,K] @ B[K,N] (+bias per col) (relu). 64x64 tile, BK=16, 256 thr.
template <bool RELU, bool BIAS>
__global__ void __launch_bounds__(256)
sgemm_kernel(const float* __restrict__ A, const float* __restrict__ B,
             const float* __restrict__ bias, float* __restrict__ C,
             int M, int N, int K) {
    const int BM = 64, BN = 64, BK = 16;
    __shared__ float As[BK][BM + 4];
    __shared__ float Bs[BK][BN + 4];
    int tid = threadIdx.x;
    int tx = tid & 15, ty = tid >> 4;
    int row0 = blockIdx.y * BM, col0 = blockIdx.x * BN;

    float acc[4][4];
#pragma unroll
    for (int i = 0; i < 4; i++)
#pragma unroll
        for (int j = 0; j < 4; j++) acc[i][j] = 0.0f;

    int ar = tid >> 2, ac = (tid & 3) * 4;      // A: 64 rows x 16 cols
    int br = tid >> 4, bc = (tid & 15) * 4;     // B: 16 rows x 64 cols

    for (int k0 = 0; k0 < K; k0 += BK) {
        float4 a;
        int arow = row0 + ar;
        if (arow < M)
            a = *reinterpret_cast<const float4*>(A + (size_t)arow * K + k0 + ac);
        else
            a = make_float4(0.f, 0.f, 0.f, 0.f);
        As[ac + 0][ar] = a.x;
        As[ac + 1][ar] = a.y;
        As[ac + 2][ar] = a.z;
        As[ac + 3][ar] = a.w;

        float4 b = *reinterpret_cast<const float4*>(
            B + (size_t)(k0 + br) * N + col0 + bc);
        Bs[br][bc + 0] = b.x;
        Bs[br][bc + 1] = b.y;
        Bs[br][bc + 2] = b.z;
        Bs[br][bc + 3] = b.w;
        __syncthreads();

#pragma unroll
        for (int k = 0; k < BK; k++) {
            float ra[4], rb[4];
#pragma unroll
            for (int i = 0; i < 4; i++) ra[i] = As[k][ty * 4 + i];
#pragma unroll
            for (int j = 0; j < 4; j++) rb[j] = Bs[k][tx * 4 + j];
#pragma unroll
            for (int i = 0; i < 4; i++)
#pragma unroll
                for (int j = 0; j < 4; j++) acc[i][j] += ra[i] * rb[j];
        }
        __syncthreads();
    }

    float bv[4];
    if (BIAS) {
#pragma unroll
        for (int j = 0; j < 4; j++) bv[j] = bias[col0 + tx * 4 + j];
    }
#pragma unroll
    for (int i = 0; i < 4; i++) {
        int r = row0 + ty * 4 + i;
        if (r >= M) continue;
        float4 o;
        float v[4];
#pragma unroll
        for (int j = 0; j < 4; j++) {
            v[j] = acc[i][j];
            if (BIAS) v[j] += bv[j];
            if (RELU) v[j] = fmaxf(v[j], 0.0f);
        }
        o.x = v[0]; o.y = v[1]; o.z = v[2]; o.w = v[3];
        *reinterpret_cast<float4*>(C + (size_t)r * N + col0 + tx * 4) = o;
    }
}

extern "C" void kernel_launch(void* const* d_in, const int* in_sizes, int n_in,
                              void* d_out, int out_size) {
    const float* x = (const float*)d_in[0];
    const int* ei = (const int*)d_in[1];
    const float* ew = (const float*)d_in[2];
    const float* W1 = (const float*)d_in[3];
    const float* b1 = (const float*)d_in[4];
    const float* W2 = (const float*)d_in[5];
    const float* b2 = (const float*)d_in[6];
    float* out = (float*)d_out;

    float *deg, *dinv, *y, *h, *z;
    cudaGetSymbolAddress((void**)&deg, g_deg);
    cudaGetSymbolAddress((void**)&dinv, g_dinv);
    cudaGetSymbolAddress((void**)&y, g_y);
    cudaGetSymbolAddress((void**)&h, g_h);
    cudaGetSymbolAddress((void**)&z, g_z);

    // 1) degrees + normalization factors
    init_deg_kernel<<<(NN + 255) / 256, 256>>>(deg, NN);
    accum_deg_kernel<<<(NE + 255) / 256, 256>>>(ei, ew, deg, NE);
    dinv_kernel<<<(NN + 255) / 256, 256>>>(deg, dinv, NN);

    // 2) y = Â x   (self-loop init, then edge scatter)
    self_init_kernel<INF / 4, false><<<(NN * (INF / 4) + 255) / 256, 256>>>(
        (const float4*)x, dinv, nullptr, (float4*)y, NN);
    scatter_kernel<128><<<(NE + 7) / 8, 256>>>(ei, ew, dinv, x, y, NE);

    // 3) h = relu(y @ W1 + b1)
    {
        dim3 grid(HIDF / 64, (NN + 63) / 64);
        sgemm_kernel<true, true><<<grid, 256>>>(y, W1, b1, h, NN, HIDF, INF);
    }

    // 4) z = h @ W2
    {
        dim3 grid(OUTF / 64, (NN + 63) / 64);
        sgemm_kernel<false, false><<<grid, 256>>>(h, W2, nullptr, z, NN, OUTF, HIDF);
    }

    // 5) out = Â z + b2
    self_init_kernel<OUTF / 4, true><<<(NN * (OUTF / 4) + 255) / 256, 256>>>(
        (const float4*)z, dinv, (const float4*)b2, (float4*)out, NN);
    scatter_kernel<64><<<(NE + 7) / 8, 256>>>(ei, ew, dinv, z, out, NE);
}

// round 4
// speedup vs baseline: 1.7922x; 1.7922x over previous
#include <cuda_runtime.h>
#include <cuda_bf16.h>
#include <cstdint>

#define NN 100000
#define NE 400000
#define INF 128
#define HIDF 1024
#define OUTF 64

// ---------------- scratch (device globals; no allocation allowed) ----------------
__device__ float g_deg[NN];
__device__ float g_dinv[NN];
__device__ __align__(256) float g_y[(size_t)NN * INF];     // aggregated x (fp32)
__device__ __align__(256) float g_h[(size_t)NN * HIDF];    // relu(yW1+b1) fp32
__device__ __align__(256) float g_z[(size_t)NN * OUTF];    // h@W2 fp32
__device__ __align__(256) float g_w1t[(size_t)HIDF * INF]; // W1^T [1024,128] tf32-rounded
__device__ __align__(256) float g_w2t[(size_t)OUTF * HIDF];// W2^T [64,1024] tf32-rounded

// ---------------- helpers ----------------
__device__ __forceinline__ uint32_t f2tf32(float x) {
    uint32_t r;
    asm("cvt.rna.tf32.f32 %0, %1;" : "=r"(r) : "f"(x));
    return r;
}
__device__ __forceinline__ void mma16n8k8(float* c, const uint32_t* a, const uint32_t* b) {
    asm volatile(
        "mma.sync.aligned.m16n8k8.row.col.f32.tf32.tf32.f32 "
        "{%0,%1,%2,%3}, {%4,%5,%6,%7}, {%8,%9}, {%0,%1,%2,%3};"
        : "+f"(c[0]), "+f"(c[1]), "+f"(c[2]), "+f"(c[3])
        : "r"(a[0]), "r"(a[1]), "r"(a[2]), "r"(a[3]), "r"(b[0]), "r"(b[1]));
}

// ---------------- graph prep kernels ----------------
__global__ void init_deg_kernel(float* __restrict__ deg, int n) {
    int i = blockIdx.x * blockDim.x + threadIdx.x;
    if (i < n) deg[i] = 1.0f;
}
__global__ void accum_deg_kernel(const int* __restrict__ ei, const float* __restrict__ ew,
                                 float* __restrict__ deg, int E) {
    int e = blockIdx.x * blockDim.x + threadIdx.x;
    if (e < E) atomicAdd(&deg[ei[E + e]], ew[e]);
}
__global__ void dinv_kernel(const float* __restrict__ deg, float* __restrict__ dinv, int n) {
    int i = blockIdx.x * blockDim.x + threadIdx.x;
    if (i < n) {
        float d = deg[i];
        dinv[i] = d > 0.0f ? rsqrtf(d) : 0.0f;
    }
}
template <int VEC_PER_ROW, bool BIAS>
__global__ void self_init_kernel(const float4* __restrict__ xin, const float* __restrict__ dinv,
                                 const float4* __restrict__ bias4, float4* __restrict__ out, int n) {
    int idx = blockIdx.x * blockDim.x + threadIdx.x;
    int total = n * VEC_PER_ROW;
    if (idx >= total) return;
    int i = idx / VEC_PER_ROW;
    int v = idx - i * VEC_PER_ROW;
    float s = dinv[i];
    s = s * s;
    float4 x = xin[idx];
    float4 r;
    r.x = s * x.x; r.y = s * x.y; r.z = s * x.z; r.w = s * x.w;
    if (BIAS) {
        float4 b = bias4[v];
        r.x += b.x; r.y += b.y; r.z += b.z; r.w += b.w;
    }
    out[idx] = r;
}
template <int F>
__global__ void scatter_kernel(const int* __restrict__ ei, const float* __restrict__ ew,
                               const float* __restrict__ dinv, const float* __restrict__ feat,
                               float* __restrict__ out, int E) {
    int warp = (blockIdx.x * blockDim.x + threadIdx.x) >> 5;
    int lane = threadIdx.x & 31;
    if (warp >= E) return;
    int s = 0, d = 0;
    float norm = 0.0f;
    if (lane == 0) {
        s = ei[warp];
        d = ei[E + warp];
        norm = dinv[s] * ew[warp] * dinv[d];
    }
    s = __shfl_sync(0xffffffffu, s, 0);
    d = __shfl_sync(0xffffffffu, d, 0);
    norm = __shfl_sync(0xffffffffu, norm, 0);
    if (F == 128) {
        float4 v = reinterpret_cast<const float4*>(feat + (size_t)s * 128)[lane];
        float* o = out + (size_t)d * 128 + lane * 4;
        atomicAdd(o + 0, norm * v.x);
        atomicAdd(o + 1, norm * v.y);
        atomicAdd(o + 2, norm * v.z);
        atomicAdd(o + 3, norm * v.w);
    } else {
        float2 v = reinterpret_cast<const float2*>(feat + (size_t)s * 64)[lane];
        float* o = out + (size_t)d * 64 + lane * 2;
        atomicAdd(o + 0, norm * v.x);
        atomicAdd(o + 1, norm * v.y);
    }
}

// W[K,N] -> Wt[N,K], tf32-rounded fp32
__global__ void wtrans_kernel(const float* __restrict__ W, float* __restrict__ Wt, int K, int N) {
    int idx = blockIdx.x * blockDim.x + threadIdx.x;
    if (idx >= K * N) return;
    int k = idx / N, n = idx - k * N;
    Wt[(size_t)n * K + k] = __uint_as_float(f2tf32(W[idx]));
}

// ---------------- TF32 mma.sync GEMM ----------------
// C[M,N] = A[M,K] @ Bt[N,K]^T (+bias)(relu). BM=128 BN=64 BK=16, 256 thr (8 warps 4x2).
template <bool RELU, bool BIAS>
__global__ void __launch_bounds__(256) gemm_mma_kernel(
    const float* __restrict__ A, const float* __restrict__ Bt,
    const float* __restrict__ bias, float* __restrict__ C, int M, int N, int K) {
    __shared__ uint32_t As[128][20];  // [row][k], pad->stride 20 (conflict-free frags)
    __shared__ uint32_t Bs[64][20];   // [n][k]
    int tid = threadIdx.x, lane = tid & 31, wid = tid >> 5;
    int wm = wid & 3, wn = wid >> 2;            // 4 m-warps x 2 n-warps
    int m0 = blockIdx.y * 128, n0 = blockIdx.x * 64;

    float acc[2][4][4];
#pragma unroll
    for (int mt = 0; mt < 2; mt++)
#pragma unroll
        for (int nt = 0; nt < 4; nt++)
#pragma unroll
            for (int i = 0; i < 4; i++) acc[mt][nt][i] = 0.0f;

    int ar = lane >> 2, ac = lane & 3;

    for (int k0 = 0; k0 < K; k0 += 16) {
        // stage A: 128x16, 2 float4 per thread
#pragma unroll
        for (int i = 0; i < 2; i++) {
            int u = tid + i * 256;          // 0..511
            int r = u >> 2, c = (u & 3) * 4;
            float4 v;
            if (m0 + r < M)
                v = *reinterpret_cast<const float4*>(A + (size_t)(m0 + r) * K + k0 + c);
            else
                v = make_float4(0.f, 0.f, 0.f, 0.f);
            As[r][c + 0] = f2tf32(v.x);
            As[r][c + 1] = f2tf32(v.y);
            As[r][c + 2] = f2tf32(v.z);
            As[r][c + 3] = f2tf32(v.w);
        }
        // stage B: 64x16, 1 float4 per thread (Bt already tf32-rounded)
        {
            int r = tid >> 2, c = (tid & 3) * 4;
            float4 v = *reinterpret_cast<const float4*>(Bt + (size_t)(n0 + r) * K + k0 + c);
            Bs[r][c + 0] = __float_as_uint(v.x);
            Bs[r][c + 1] = __float_as_uint(v.y);
            Bs[r][c + 2] = __float_as_uint(v.z);
            Bs[r][c + 3] = __float_as_uint(v.w);
        }
        __syncthreads();
#pragma unroll
        for (int kk = 0; kk < 16; kk += 8) {
            uint32_t a[2][4], b[4][2];
#pragma unroll
            for (int mt = 0; mt < 2; mt++) {
                int rb = wm * 32 + mt * 16;
                a[mt][0] = As[rb + ar][kk + ac];
                a[mt][1] = As[rb + ar + 8][kk + ac];
                a[mt][2] = As[rb + ar][kk + ac + 4];
                a[mt][3] = As[rb + ar + 8][kk + ac + 4];
            }
#pragma unroll
            for (int nt = 0; nt < 4; nt++) {
                int nb = wn * 32 + nt * 8 + ar;
                b[nt][0] = Bs[nb][kk + ac];
                b[nt][1] = Bs[nb][kk + ac + 4];
            }
#pragma unroll
            for (int mt = 0; mt < 2; mt++)
#pragma unroll
                for (int nt = 0; nt < 4; nt++) mma16n8k8(acc[mt][nt], a[mt], b[nt]);
        }
        __syncthreads();
    }

    // epilogue: c0,c1 -> (row, col..col+1); c2,c3 -> (row+8, ...)
#pragma unroll
    for (int mt = 0; mt < 2; mt++) {
#pragma unroll
        for (int half = 0; half < 2; half++) {
            int row = m0 + wm * 32 + mt * 16 + ar + half * 8;
            if (row >= M) continue;
#pragma unroll
            for (int nt = 0; nt < 4; nt++) {
                int col = n0 + wn * 32 + nt * 8 + 2 * ac;
                float v0 = acc[mt][nt][half * 2 + 0];
                float v1 = acc[mt][nt][half * 2 + 1];
                if (BIAS) { v0 += bias[col]; v1 += bias[col + 1]; }
                if (RELU) { v0 = fmaxf(v0, 0.0f); v1 = fmaxf(v1, 0.0f); }
                *reinterpret_cast<float2*>(C + (size_t)row * N + col) = make_float2(v0, v1);
            }
        }
    }
}

// ---------------- launch ----------------
extern "C" void kernel_launch(void* const* d_in, const int* in_sizes, int n_in,
                              void* d_out, int out_size) {
    const float* x = (const float*)d_in[0];
    const int* ei = (const int*)d_in[1];
    const float* ew = (const float*)d_in[2];
    const float* W1 = (const float*)d_in[3];
    const float* b1 = (const float*)d_in[4];
    const float* W2 = (const float*)d_in[5];
    const float* b2 = (const float*)d_in[6];
    float* out = (float*)d_out;

    float *deg, *dinv, *y, *h, *z, *w1t, *w2t;
    cudaGetSymbolAddress((void**)&deg, g_deg);
    cudaGetSymbolAddress((void**)&dinv, g_dinv);
    cudaGetSymbolAddress((void**)&y, g_y);
    cudaGetSymbolAddress((void**)&h, g_h);
    cudaGetSymbolAddress((void**)&z, g_z);
    cudaGetSymbolAddress((void**)&w1t, g_w1t);
    cudaGetSymbolAddress((void**)&w2t, g_w2t);

    // 1) degrees + norm
    init_deg_kernel<<<(NN + 255) / 256, 256>>>(deg, NN);
    accum_deg_kernel<<<(NE + 255) / 256, 256>>>(ei, ew, deg, NE);
    dinv_kernel<<<(NN + 255) / 256, 256>>>(deg, dinv, NN);

    // 2) y = Â x
    self_init_kernel<INF / 4, false><<<(NN * (INF / 4) + 255) / 256, 256>>>(
        (const float4*)x, dinv, nullptr, (float4*)y, NN);
    scatter_kernel<128><<<(NE + 7) / 8, 256>>>(ei, ew, dinv, x, y, NE);

    // 3) transpose + tf32-round weights
    wtrans_kernel<<<(INF * HIDF + 255) / 256, 256>>>(W1, w1t, INF, HIDF);
    wtrans_kernel<<<(HIDF * OUTF + 255) / 256, 256>>>(W2, w2t, HIDF, OUTF);

    // 4) h = relu(y @ W1 + b1)
    {
        dim3 grid(HIDF / 64, (NN + 127) / 128);
        gemm_mma_kernel<true, true><<<grid, 256>>>(y, w1t, b1, h, NN, HIDF, INF);
    }
    // 5) z = h @ W2
    {
        dim3 grid(OUTF / 64, (NN + 127) / 128);
        gemm_mma_kernel<false, false><<<grid, 256>>>(h, w2t, nullptr, z, NN, OUTF, HIDF);
    }
    // 6) out = Â z + b2
    self_init_kernel<OUTF / 4, true><<<(NN * (OUTF / 4) + 255) / 256, 256>>>(
        (const float4*)z, dinv, (const float4*)b2, (float4*)out, NN);
    scatter_kernel<64><<<(NE + 7) / 8, 256>>>(ei, ew, dinv, z, out, NE);
}

// round 6
// speedup vs baseline: 2.0670x; 1.1533x over previous
#include <cuda_runtime.h>
#include <cuda_bf16.h>
#include <cstdint>

#define NN 100000
#define NE 400000
#define INF 128
#define HIDF 1024
#define OUTF 64
#define SCAN_B 1024
#define NBLK ((NN + SCAN_B - 1) / SCAN_B)

// ---------------- scratch (device globals; no allocation allowed) ----------------
__device__ float g_deg[NN];
__device__ float g_dinv[NN];
__device__ int g_cnt[NN];
__device__ int g_inc[NN];
__device__ int g_bsum[NBLK];
__device__ int g_offs[NN];
__device__ int g_fill[NN];
__device__ int g_csr_src[NE];
__device__ float g_csr_nrm[NE];
__device__ __align__(256) float g_y[(size_t)NN * INF];
__device__ __align__(256) float g_h[(size_t)NN * HIDF];
__device__ __align__(256) float g_z[(size_t)NN * OUTF];
__device__ __align__(256) float g_w1t[(size_t)HIDF * INF];
__device__ __align__(256) float g_w2t[(size_t)OUTF * HIDF];

// ---------------- helpers ----------------
__device__ __forceinline__ uint32_t f2tf32(float x) {
    uint32_t r;
    asm("cvt.rna.tf32.f32 %0, %1;" : "=r"(r) : "f"(x));
    return r;
}
__device__ __forceinline__ void mma16n8k8(float* c, const uint32_t* a, const uint32_t* b) {
    asm volatile(
        "mma.sync.aligned.m16n8k8.row.col.f32.tf32.tf32.f32 "
        "{%0,%1,%2,%3}, {%4,%5,%6,%7}, {%8,%9}, {%0,%1,%2,%3};"
        : "+f"(c[0]), "+f"(c[1]), "+f"(c[2]), "+f"(c[3])
        : "r"(a[0]), "r"(a[1]), "r"(a[2]), "r"(a[3]), "r"(b[0]), "r"(b[1]));
}

// ---------------- graph prep ----------------
__global__ void init_kernel(float* __restrict__ deg, int* __restrict__ cnt,
                            int* __restrict__ fill, int n) {
    int i = blockIdx.x * blockDim.x + threadIdx.x;
    if (i < n) { deg[i] = 1.0f; cnt[i] = 0; fill[i] = 0; }
}
__global__ void accum_kernel(const int* __restrict__ ei, const float* __restrict__ ew,
                             float* __restrict__ deg, int* __restrict__ cnt, int E) {
    int e = blockIdx.x * blockDim.x + threadIdx.x;
    if (e < E) {
        int d = ei[E + e];
        atomicAdd(&deg[d], ew[e]);
        atomicAdd(&cnt[d], 1);
    }
}
__global__ void dinv_kernel(const float* __restrict__ deg, float* __restrict__ dinv, int n) {
    int i = blockIdx.x * blockDim.x + threadIdx.x;
    if (i < n) {
        float d = deg[i];
        dinv[i] = d > 0.0f ? rsqrtf(d) : 0.0f;
    }
}
// inclusive block scan
__global__ void scan_block_kernel(const int* __restrict__ cnt, int* __restrict__ inc,
                                  int* __restrict__ bsum, int n) {
    __shared__ int s[SCAN_B];
    int i = blockIdx.x * SCAN_B + threadIdx.x;
    int v = (i < n) ? cnt[i] : 0;
    s[threadIdx.x] = v;
    __syncthreads();
    for (int d = 1; d < SCAN_B; d <<= 1) {
        int t = (threadIdx.x >= d) ? s[threadIdx.x - d] : 0;
        __syncthreads();
        s[threadIdx.x] += t;
        __syncthreads();
    }
    if (i < n) inc[i] = s[threadIdx.x];
    if (threadIdx.x == SCAN_B - 1) bsum[blockIdx.x] = s[SCAN_B - 1];
}
__global__ void scan_bsum_kernel(int* __restrict__ bsum, int nb) {
    if (threadIdx.x == 0 && blockIdx.x == 0) {
        int acc = 0;
        for (int b = 0; b < nb; b++) { int t = bsum[b]; bsum[b] = acc; acc += t; }
    }
}
__global__ void scan_final_kernel(const int* __restrict__ cnt, const int* __restrict__ inc,
                                  const int* __restrict__ bsum, int* __restrict__ offs, int n) {
    int i = blockIdx.x * SCAN_B + threadIdx.x;
    if (i < n) offs[i] = bsum[blockIdx.x] + inc[i] - cnt[i];
}
__global__ void fill_csr_kernel(const int* __restrict__ ei, const float* __restrict__ ew,
                                const float* __restrict__ dinv, const int* __restrict__ offs,
                                int* __restrict__ fill, int* __restrict__ csr_src,
                                float* __restrict__ csr_nrm, int E) {
    int e = blockIdx.x * blockDim.x + threadIdx.x;
    if (e >= E) return;
    int s = ei[e], d = ei[E + e];
    int pos = offs[d] + atomicAdd(&fill[d], 1);
    csr_src[pos] = s;
    csr_nrm[pos] = dinv[s] * ew[e] * dinv[d];
}

// one warp per dst node: out[i] = selfnorm*feat[i] + sum_j nrm_j*feat[src_j] (+bias)
template <int F, bool BIAS>
__global__ void gather_kernel(const int* __restrict__ csr_src, const float* __restrict__ csr_nrm,
                              const int* __restrict__ offs, const int* __restrict__ cnt,
                              const float* __restrict__ dinv, const float* __restrict__ feat,
                              const float* __restrict__ bias, float* __restrict__ out) {
    int warp = (blockIdx.x * blockDim.x + threadIdx.x) >> 5;
    int lane = threadIdx.x & 31;
    if (warp >= NN) return;
    int beg = offs[warp], n = cnt[warp];
    float si = dinv[warp];
    si = si * si;
    if (F == 128) {
        float4 v = reinterpret_cast<const float4*>(feat + (size_t)warp * 128)[lane];
        float4 acc;
        acc.x = si * v.x; acc.y = si * v.y; acc.z = si * v.z; acc.w = si * v.w;
        for (int j = beg; j < beg + n; j++) {
            int s = csr_src[j];
            float nrm = csr_nrm[j];
            float4 f = reinterpret_cast<const float4*>(feat + (size_t)s * 128)[lane];
            acc.x += nrm * f.x; acc.y += nrm * f.y; acc.z += nrm * f.z; acc.w += nrm * f.w;
        }
        reinterpret_cast<float4*>(out + (size_t)warp * 128)[lane] = acc;
    } else {  // 64
        float2 v = reinterpret_cast<const float2*>(feat + (size_t)warp * 64)[lane];
        float2 acc;
        acc.x = si * v.x; acc.y = si * v.y;
        for (int j = beg; j < beg + n; j++) {
            int s = csr_src[j];
            float nrm = csr_nrm[j];
            float2 f = reinterpret_cast<const float2*>(feat + (size_t)s * 64)[lane];
            acc.x += nrm * f.x; acc.y += nrm * f.y;
        }
        if (BIAS) {
            float2 b = reinterpret_cast<const float2*>(bias)[lane];
            acc.x += b.x; acc.y += b.y;
        }
        reinterpret_cast<float2*>(out + (size_t)warp * 64)[lane] = acc;
    }
}

// W[K,N] -> Wt[N,K], tf32-rounded fp32
__global__ void wtrans_kernel(const float* __restrict__ W, float* __restrict__ Wt, int K, int N) {
    int idx = blockIdx.x * blockDim.x + threadIdx.x;
    if (idx >= K * N) return;
    int k = idx / N, n = idx - k * N;
    Wt[(size_t)n * K + k] = __uint_as_float(f2tf32(W[idx]));
}

// ---------------- TF32 mma.sync GEMM (BM=128 BN=64 BK=16, 8 warps 4x2) ----------------
template <bool RELU, bool BIAS>
__global__ void __launch_bounds__(256) gemm_mma_kernel(
    const float* __restrict__ A, const float* __restrict__ Bt,
    const float* __restrict__ bias, float* __restrict__ C, int M, int N, int K) {
    __shared__ uint32_t As[128][20];
    __shared__ uint32_t Bs[64][20];
    int tid = threadIdx.x, lane = tid & 31, wid = tid >> 5;
    int wm = wid & 3, wn = wid >> 2;
    int m0 = blockIdx.y * 128, n0 = blockIdx.x * 64;

    float acc[2][4][4];
#pragma unroll
    for (int mt = 0; mt < 2; mt++)
#pragma unroll
        for (int nt = 0; nt < 4; nt++)
#pragma unroll
            for (int i = 0; i < 4; i++) acc[mt][nt][i] = 0.0f;

    int ar = lane >> 2, ac = lane & 3;

    for (int k0 = 0; k0 < K; k0 += 16) {
#pragma unroll
        for (int i = 0; i < 2; i++) {
            int u = tid + i * 256;
            int r = u >> 2, c = (u & 3) * 4;
            float4 v;
            if (m0 + r < M)
                v = *reinterpret_cast<const float4*>(A + (size_t)(m0 + r) * K + k0 + c);
            else
                v = make_float4(0.f, 0.f, 0.f, 0.f);
            As[r][c + 0] = f2tf32(v.x);
            As[r][c + 1] = f2tf32(v.y);
            As[r][c + 2] = f2tf32(v.z);
            As[r][c + 3] = f2tf32(v.w);
        }
        {
            int r = tid >> 2, c = (tid & 3) * 4;
            float4 v = *reinterpret_cast<const float4*>(Bt + (size_t)(n0 + r) * K + k0 + c);
            Bs[r][c + 0] = __float_as_uint(v.x);
            Bs[r][c + 1] = __float_as_uint(v.y);
            Bs[r][c + 2] = __float_as_uint(v.z);
            Bs[r][c + 3] = __float_as_uint(v.w);
        }
        __syncthreads();
#pragma unroll
        for (int kk = 0; kk < 16; kk += 8) {
            uint32_t a[2][4], b[4][2];
#pragma unroll
            for (int mt = 0; mt < 2; mt++) {
                int rb = wm * 32 + mt * 16;
                a[mt][0] = As[rb + ar][kk + ac];
                a[mt][1] = As[rb + ar + 8][kk + ac];
                a[mt][2] = As[rb + ar][kk + ac + 4];
                a[mt][3] = As[rb + ar + 8][kk + ac + 4];
            }
#pragma unroll
            for (int nt = 0; nt < 4; nt++) {
                int nb = wn * 32 + nt * 8 + ar;
                b[nt][0] = Bs[nb][kk + ac];
                b[nt][1] = Bs[nb][kk + ac + 4];
            }
#pragma unroll
            for (int mt = 0; mt < 2; mt++)
#pragma unroll
                for (int nt = 0; nt < 4; nt++) mma16n8k8(acc[mt][nt], a[mt], b[nt]);
        }
        __syncthreads();
    }

#pragma unroll
    for (int mt = 0; mt < 2; mt++) {
#pragma unroll
        for (int half = 0; half < 2; half++) {
            int row = m0 + wm * 32 + mt * 16 + ar + half * 8;
            if (row >= M) continue;
#pragma unroll
            for (int nt = 0; nt < 4; nt++) {
                int col = n0 + wn * 32 + nt * 8 + 2 * ac;
                float v0 = acc[mt][nt][half * 2 + 0];
                float v1 = acc[mt][nt][half * 2 + 1];
                if (BIAS) { v0 += bias[col]; v1 += bias[col + 1]; }
                if (RELU) { v0 = fmaxf(v0, 0.0f); v1 = fmaxf(v1, 0.0f); }
                *reinterpret_cast<float2*>(C + (size_t)row * N + col) = make_float2(v0, v1);
            }
        }
    }
}

// ---------------- launch ----------------
extern "C" void kernel_launch(void* const* d_in, const int* in_sizes, int n_in,
                              void* d_out, int out_size) {
    const float* x = (const float*)d_in[0];
    const int* ei = (const int*)d_in[1];
    const float* ew = (const float*)d_in[2];
    const float* W1 = (const float*)d_in[3];
    const float* b1 = (const float*)d_in[4];
    const float* W2 = (const float*)d_in[5];
    const float* b2 = (const float*)d_in[6];
    float* out = (float*)d_out;

    float *deg, *dinv, *y, *h, *z, *w1t, *w2t, *csr_nrm;
    int *cnt, *inc, *bsum, *offs, *fill, *csr_src;
    cudaGetSymbolAddress((void**)&deg, g_deg);
    cudaGetSymbolAddress((void**)&dinv, g_dinv);
    cudaGetSymbolAddress((void**)&y, g_y);
    cudaGetSymbolAddress((void**)&h, g_h);
    cudaGetSymbolAddress((void**)&z, g_z);
    cudaGetSymbolAddress((void**)&w1t, g_w1t);
    cudaGetSymbolAddress((void**)&w2t, g_w2t);
    cudaGetSymbolAddress((void**)&cnt, g_cnt);
    cudaGetSymbolAddress((void**)&inc, g_inc);
    cudaGetSymbolAddress((void**)&bsum, g_bsum);
    cudaGetSymbolAddress((void**)&offs, g_offs);
    cudaGetSymbolAddress((void**)&fill, g_fill);
    cudaGetSymbolAddress((void**)&csr_src, g_csr_src);
    cudaGetSymbolAddress((void**)&csr_nrm, g_csr_nrm);

    // 1) degrees + counts + norm
    init_kernel<<<(NN + 255) / 256, 256>>>(deg, cnt, fill, NN);
    accum_kernel<<<(NE + 255) / 256, 256>>>(ei, ew, deg, cnt, NE);
    dinv_kernel<<<(NN + 255) / 256, 256>>>(deg, dinv, NN);

    // 2) CSR build (exclusive scan + fill)
    scan_block_kernel<<<NBLK, SCAN_B>>>(cnt, inc, bsum, NN);
    scan_bsum_kernel<<<1, 32>>>(bsum, NBLK);
    scan_final_kernel<<<NBLK, SCAN_B>>>(cnt, inc, bsum, offs, NN);
    fill_csr_kernel<<<(NE + 255) / 256, 256>>>(ei, ew, dinv, offs, fill, csr_src, csr_nrm, NE);

    // 3) transpose + tf32-round weights (overlappable with CSR build)
    wtrans_kernel<<<(INF * HIDF + 255) / 256, 256>>>(W1, w1t, INF, HIDF);
    wtrans_kernel<<<(HIDF * OUTF + 255) / 256, 256>>>(W2, w2t, HIDF, OUTF);

    // 4) y = Â x  (gather)
    gather_kernel<128, false><<<(NN * 32 + 255) / 256, 256>>>(csr_src, csr_nrm, offs, cnt,
                                                              dinv, x, nullptr, y);
    // 5) h = relu(y @ W1 + b1)
    {
        dim3 grid(HIDF / 64, (NN + 127) / 128);
        gemm_mma_kernel<true, true><<<grid, 256>>>(y, w1t, b1, h, NN, HIDF, INF);
    }
    // 6) z = h @ W2
    {
        dim3 grid(OUTF / 64, (NN + 127) / 128);
        gemm_mma_kernel<false, false><<<grid, 256>>>(h, w2t, nullptr, z, NN, OUTF, HIDF);
    }
    // 7) out = Â z + b2  (gather)
    gather_kernel<64, true><<<(NN * 32 + 255) / 256, 256>>>(csr_src, csr_nrm, offs, cnt,
                                                            dinv, z, b2, out);
}

// round 8
// speedup vs baseline: 3.0234x; 1.4627x over previous
#include <cuda_runtime.h>
#include <cuda_bf16.h>
#include <cstdint>

#define NN 100000
#define NE 400000
#define INF 128
#define HIDF 1024
#define OUTF 64
#define SCAN_B 1024
#define NBLK ((NN + SCAN_B - 1) / SCAN_B)

// ---------------- scratch (device globals; no allocation allowed) ----------------
__device__ float g_deg[NN];
__device__ float g_dinv[NN];
__device__ int g_cnt[NN];
__device__ int g_inc[NN];
__device__ int g_bsum[NBLK];
__device__ int g_offs[NN];
__device__ int g_fill[NN];
__device__ int g_csr_src[NE];
__device__ float g_csr_nrm[NE];
__device__ __align__(256) float g_y[(size_t)NN * INF];
__device__ __align__(256) float g_z[(size_t)NN * OUTF];
__device__ __align__(256) float g_w1t[(size_t)HIDF * INF];   // [hid][in] tf32
__device__ __align__(256) float g_w2t[(size_t)OUTF * HIDF];  // [out][hid] tf32

// ---------------- helpers ----------------
__device__ __forceinline__ uint32_t f2tf32(float x) {
    uint32_t r;
    asm("cvt.rna.tf32.f32 %0, %1;" : "=r"(r) : "f"(x));
    return r;
}
__device__ __forceinline__ void mma16n8k8(float* c, const uint32_t* a, const uint32_t* b) {
    asm volatile(
        "mma.sync.aligned.m16n8k8.row.col.f32.tf32.tf32.f32 "
        "{%0,%1,%2,%3}, {%4,%5,%6,%7}, {%8,%9}, {%0,%1,%2,%3};"
        : "+f"(c[0]), "+f"(c[1]), "+f"(c[2]), "+f"(c[3])
        : "r"(a[0]), "r"(a[1]), "r"(a[2]), "r"(a[3]), "r"(b[0]), "r"(b[1]));
}

// ---------------- graph prep ----------------
__global__ void init_kernel(float* __restrict__ deg, int* __restrict__ cnt,
                            int* __restrict__ fill, int n) {
    int i = blockIdx.x * blockDim.x + threadIdx.x;
    if (i < n) { deg[i] = 1.0f; cnt[i] = 0; fill[i] = 0; }
}
__global__ void accum_kernel(const int* __restrict__ ei, const float* __restrict__ ew,
                             float* __restrict__ deg, int* __restrict__ cnt, int E) {
    int e = blockIdx.x * blockDim.x + threadIdx.x;
    if (e < E) {
        int d = ei[E + e];
        atomicAdd(&deg[d], ew[e]);
        atomicAdd(&cnt[d], 1);
    }
}
__global__ void dinv_kernel(const float* __restrict__ deg, float* __restrict__ dinv, int n) {
    int i = blockIdx.x * blockDim.x + threadIdx.x;
    if (i < n) {
        float d = deg[i];
        dinv[i] = d > 0.0f ? rsqrtf(d) : 0.0f;
    }
}
__global__ void scan_block_kernel(const int* __restrict__ cnt, int* __restrict__ inc,
                                  int* __restrict__ bsum, int n) {
    __shared__ int s[SCAN_B];
    int i = blockIdx.x * SCAN_B + threadIdx.x;
    int v = (i < n) ? cnt[i] : 0;
    s[threadIdx.x] = v;
    __syncthreads();
    for (int d = 1; d < SCAN_B; d <<= 1) {
        int t = (threadIdx.x >= d) ? s[threadIdx.x - d] : 0;
        __syncthreads();
        s[threadIdx.x] += t;
        __syncthreads();
    }
    if (i < n) inc[i] = s[threadIdx.x];
    if (threadIdx.x == SCAN_B - 1) bsum[blockIdx.x] = s[SCAN_B - 1];
}
__global__ void scan_bsum_kernel(int* __restrict__ bsum, int nb) {
    if (threadIdx.x == 0 && blockIdx.x == 0) {
        int acc = 0;
        for (int b = 0; b < nb; b++) { int t = bsum[b]; bsum[b] = acc; acc += t; }
    }
}
__global__ void scan_final_kernel(const int* __restrict__ cnt, const int* __restrict__ inc,
                                  const int* __restrict__ bsum, int* __restrict__ offs, int n) {
    int i = blockIdx.x * SCAN_B + threadIdx.x;
    if (i < n) offs[i] = bsum[blockIdx.x] + inc[i] - cnt[i];
}
__global__ void fill_csr_kernel(const int* __restrict__ ei, const float* __restrict__ ew,
                                const float* __restrict__ dinv, const int* __restrict__ offs,
                                int* __restrict__ fill, int* __restrict__ csr_src,
                                float* __restrict__ csr_nrm, int E) {
    int e = blockIdx.x * blockDim.x + threadIdx.x;
    if (e >= E) return;
    int s = ei[e], d = ei[E + e];
    int pos = offs[d] + atomicAdd(&fill[d], 1);
    csr_src[pos] = s;
    csr_nrm[pos] = dinv[s] * ew[e] * dinv[d];
}

// one warp per dst node
template <int F, bool BIAS>
__global__ void gather_kernel(const int* __restrict__ csr_src, const float* __restrict__ csr_nrm,
                              const int* __restrict__ offs, const int* __restrict__ cnt,
                              const float* __restrict__ dinv, const float* __restrict__ feat,
                              const float* __restrict__ bias, float* __restrict__ out) {
    int warp = (blockIdx.x * blockDim.x + threadIdx.x) >> 5;
    int lane = threadIdx.x & 31;
    if (warp >= NN) return;
    int beg = offs[warp], n = cnt[warp];
    float si = dinv[warp];
    si = si * si;
    if (F == 128) {
        float4 v = reinterpret_cast<const float4*>(feat + (size_t)warp * 128)[lane];
        float4 acc;
        acc.x = si * v.x; acc.y = si * v.y; acc.z = si * v.z; acc.w = si * v.w;
        for (int j = beg; j < beg + n; j++) {
            int s = csr_src[j];
            float nrm = csr_nrm[j];
            float4 f = reinterpret_cast<const float4*>(feat + (size_t)s * 128)[lane];
            acc.x += nrm * f.x; acc.y += nrm * f.y; acc.z += nrm * f.z; acc.w += nrm * f.w;
        }
        reinterpret_cast<float4*>(out + (size_t)warp * 128)[lane] = acc;
    } else {
        float2 v = reinterpret_cast<const float2*>(feat + (size_t)warp * 64)[lane];
        float2 acc;
        acc.x = si * v.x; acc.y = si * v.y;
        for (int j = beg; j < beg + n; j++) {
            int s = csr_src[j];
            float nrm = csr_nrm[j];
            float2 f = reinterpret_cast<const float2*>(feat + (size_t)s * 64)[lane];
            acc.x += nrm * f.x; acc.y += nrm * f.y;
        }
        if (BIAS) {
            float2 b = reinterpret_cast<const float2*>(bias)[lane];
            acc.x += b.x; acc.y += b.y;
        }
        reinterpret_cast<float2*>(out + (size_t)warp * 64)[lane] = acc;
    }
}

// W[K,N] -> Wt[N,K], tf32-rounded
__global__ void wtrans_kernel(const float* __restrict__ W, float* __restrict__ Wt, int K, int N) {
    int idx = blockIdx.x * blockDim.x + threadIdx.x;
    if (idx >= K * N) return;
    int k = idx / N, n = idx - k * N;
    Wt[(size_t)n * K + k] = __uint_as_float(f2tf32(W[idx]));
}

// ---------------- fused 2-layer GEMM ----------------
// Z[128-tile, 64] = relu(Y_tile @ W1 + b1) @ W2, h never leaves SMEM.
// 8 warps as 4(m) x 2(n). SMEM: As 128x132, Bs 64x132, Hs 128x68, W2s 64x68 (u32).
#define AS_STR 132
#define HS_STR 68
#define OFF_AS 0
#define OFF_BS (128 * AS_STR)
#define OFF_HS (OFF_BS + 64 * AS_STR)
#define OFF_W2 (OFF_HS + 128 * HS_STR)
#define FUSED_SMEM ((OFF_W2 + 64 * HS_STR) * 4)

__global__ void __launch_bounds__(256) fused_gemm_kernel(
    const float* __restrict__ Y, const float* __restrict__ W1t,
    const float* __restrict__ b1, const float* __restrict__ W2t,
    float* __restrict__ Z, int M) {
    extern __shared__ uint32_t sm[];
    uint32_t* As = sm + OFF_AS;   // [128][132] y tile (tf32)
    uint32_t* Bs = sm + OFF_BS;   // [64][132]  W1 chunk
    uint32_t* Hs = sm + OFF_HS;   // [128][68]  h chunk (tf32)
    uint32_t* W2s = sm + OFF_W2;  // [64][68]   W2 chunk

    int tid = threadIdx.x, lane = tid & 31, wid = tid >> 5;
    int wm = wid & 3, wn = wid >> 2;
    int m0 = blockIdx.x * 128;
    int ar = lane >> 2, ac = lane & 3;

    // stage Y tile once: 128x128 floats -> tf32
#pragma unroll
    for (int i = 0; i < 16; i++) {
        int u = tid + i * 256;          // 0..4095
        int r = u >> 5, c = (u & 31) * 4;
        float4 v;
        if (m0 + r < M)
            v = *reinterpret_cast<const float4*>(Y + (size_t)(m0 + r) * INF + c);
        else
            v = make_float4(0.f, 0.f, 0.f, 0.f);
        uint32_t* p = As + r * AS_STR + c;
        p[0] = f2tf32(v.x); p[1] = f2tf32(v.y); p[2] = f2tf32(v.z); p[3] = f2tf32(v.w);
    }

    float acc_out[2][4][4];
#pragma unroll
    for (int mt = 0; mt < 2; mt++)
#pragma unroll
        for (int nt = 0; nt < 4; nt++)
#pragma unroll
            for (int i = 0; i < 4; i++) acc_out[mt][nt][i] = 0.0f;

    for (int ch = 0; ch < HIDF / 64; ch++) {
        int c0 = ch * 64;
        __syncthreads();  // As ready (ch=0); prev mma2 done reading Bs/W2s/Hs (ch>0)
        // load W1 chunk [64 hid x 128 k]
#pragma unroll
        for (int i = 0; i < 8; i++) {
            int u = tid + i * 256;      // 0..2047
            int r = u >> 5, c = (u & 31) * 4;
            float4 v = *reinterpret_cast<const float4*>(W1t + (size_t)(c0 + r) * INF + c);
            uint32_t* p = Bs + r * AS_STR + c;
            p[0] = __float_as_uint(v.x); p[1] = __float_as_uint(v.y);
            p[2] = __float_as_uint(v.z); p[3] = __float_as_uint(v.w);
        }
        // load W2 chunk [64 out x 64 k]
#pragma unroll
        for (int i = 0; i < 4; i++) {
            int u = tid + i * 256;      // 0..1023
            int r = u >> 4, c = (u & 15) * 4;
            float4 v = *reinterpret_cast<const float4*>(W2t + (size_t)r * HIDF + c0 + c);
            uint32_t* p = W2s + r * HS_STR + c;
            p[0] = __float_as_uint(v.x); p[1] = __float_as_uint(v.y);
            p[2] = __float_as_uint(v.z); p[3] = __float_as_uint(v.w);
        }
        __syncthreads();

        // mma1: h_chunk[128x64] = y_tile @ W1chunk^T over K=128
        float acc_h[2][4][4];
#pragma unroll
        for (int mt = 0; mt < 2; mt++)
#pragma unroll
            for (int nt = 0; nt < 4; nt++)
#pragma unroll
                for (int i = 0; i < 4; i++) acc_h[mt][nt][i] = 0.0f;
#pragma unroll
        for (int kk = 0; kk < 128; kk += 8) {
            uint32_t a[2][4], b[4][2];
#pragma unroll
            for (int mt = 0; mt < 2; mt++) {
                int rb = wm * 32 + mt * 16;
                const uint32_t* p0 = As + (rb + ar) * AS_STR + kk + ac;
                const uint32_t* p1 = As + (rb + ar + 8) * AS_STR + kk + ac;
                a[mt][0] = p0[0]; a[mt][1] = p1[0]; a[mt][2] = p0[4]; a[mt][3] = p1[4];
            }
#pragma unroll
            for (int nt = 0; nt < 4; nt++) {
                const uint32_t* p = Bs + (wn * 32 + nt * 8 + ar) * AS_STR + kk + ac;
                b[nt][0] = p[0]; b[nt][1] = p[4];
            }
#pragma unroll
            for (int mt = 0; mt < 2; mt++)
#pragma unroll
                for (int nt = 0; nt < 4; nt++) mma16n8k8(acc_h[mt][nt], a[mt], b[nt]);
        }
        // bias + relu, write h chunk to SMEM as tf32
#pragma unroll
        for (int mt = 0; mt < 2; mt++) {
#pragma unroll
            for (int half = 0; half < 2; half++) {
                int row = wm * 32 + mt * 16 + ar + half * 8;
#pragma unroll
                for (int nt = 0; nt < 4; nt++) {
                    int col = wn * 32 + nt * 8 + 2 * ac;
                    float bv0 = __ldg(b1 + c0 + col);
                    float bv1 = __ldg(b1 + c0 + col + 1);
                    float v0 = fmaxf(acc_h[mt][nt][half * 2 + 0] + bv0, 0.0f);
                    float v1 = fmaxf(acc_h[mt][nt][half * 2 + 1] + bv1, 0.0f);
                    uint32_t* p = Hs + row * HS_STR + col;
                    p[0] = f2tf32(v0);
                    p[1] = f2tf32(v1);
                }
            }
        }
        __syncthreads();

        // mma2: acc_out += h_chunk @ W2chunk^T over K=64
#pragma unroll
        for (int kk = 0; kk < 64; kk += 8) {
            uint32_t a[2][4], b[4][2];
#pragma unroll
            for (int mt = 0; mt < 2; mt++) {
                int rb = wm * 32 + mt * 16;
                const uint32_t* p0 = Hs + (rb + ar) * HS_STR + kk + ac;
                const uint32_t* p1 = Hs + (rb + ar + 8) * HS_STR + kk + ac;
                a[mt][0] = p0[0]; a[mt][1] = p1[0]; a[mt][2] = p0[4]; a[mt][3] = p1[4];
            }
#pragma unroll
            for (int nt = 0; nt < 4; nt++) {
                const uint32_t* p = W2s + (wn * 32 + nt * 8 + ar) * HS_STR + kk + ac;
                b[nt][0] = p[0]; b[nt][1] = p[4];
            }
#pragma unroll
            for (int mt = 0; mt < 2; mt++)
#pragma unroll
                for (int nt = 0; nt < 4; nt++) mma16n8k8(acc_out[mt][nt], a[mt], b[nt]);
        }
    }

    // epilogue: Z tile [128 x 64]
#pragma unroll
    for (int mt = 0; mt < 2; mt++) {
#pragma unroll
        for (int half = 0; half < 2; half++) {
            int row = m0 + wm * 32 + mt * 16 + ar + half * 8;
            if (row >= M) continue;
#pragma unroll
            for (int nt = 0; nt < 4; nt++) {
                int col = wn * 32 + nt * 8 + 2 * ac;
                *reinterpret_cast<float2*>(Z + (size_t)row * OUTF + col) =
                    make_float2(acc_out[mt][nt][half * 2 + 0], acc_out[mt][nt][half * 2 + 1]);
            }
        }
    }
}

// ---------------- launch ----------------
extern "C" void kernel_launch(void* const* d_in, const int* in_sizes, int n_in,
                              void* d_out, int out_size) {
    const float* x = (const float*)d_in[0];
    const int* ei = (const int*)d_in[1];
    const float* ew = (const float*)d_in[2];
    const float* W1 = (const float*)d_in[3];
    const float* b1 = (const float*)d_in[4];
    const float* W2 = (const float*)d_in[5];
    const float* b2 = (const float*)d_in[6];
    float* out = (float*)d_out;

    float *deg, *dinv, *y, *z, *w1t, *w2t, *csr_nrm;
    int *cnt, *inc, *bsum, *offs, *fill, *csr_src;
    cudaGetSymbolAddress((void**)&deg, g_deg);
    cudaGetSymbolAddress((void**)&dinv, g_dinv);
    cudaGetSymbolAddress((void**)&y, g_y);
    cudaGetSymbolAddress((void**)&z, g_z);
    cudaGetSymbolAddress((void**)&w1t, g_w1t);
    cudaGetSymbolAddress((void**)&w2t, g_w2t);
    cudaGetSymbolAddress((void**)&cnt, g_cnt);
    cudaGetSymbolAddress((void**)&inc, g_inc);
    cudaGetSymbolAddress((void**)&bsum, g_bsum);
    cudaGetSymbolAddress((void**)&offs, g_offs);
    cudaGetSymbolAddress((void**)&fill, g_fill);
    cudaGetSymbolAddress((void**)&csr_src, g_csr_src);
    cudaGetSymbolAddress((void**)&csr_nrm, g_csr_nrm);

    static bool attr_set = false;
    if (!attr_set) {
        cudaFuncSetAttribute(fused_gemm_kernel,
                             cudaFuncAttributeMaxDynamicSharedMemorySize, FUSED_SMEM);
        attr_set = true;
    }

    // 1) degrees + counts + norm
    init_kernel<<<(NN + 255) / 256, 256>>>(deg, cnt, fill, NN);
    accum_kernel<<<(NE + 255) / 256, 256>>>(ei, ew, deg, cnt, NE);
    dinv_kernel<<<(NN + 255) / 256, 256>>>(deg, dinv, NN);

    // 2) CSR build
    scan_block_kernel<<<NBLK, SCAN_B>>>(cnt, inc, bsum, NN);
    scan_bsum_kernel<<<1, 32>>>(bsum, NBLK);
    scan_final_kernel<<<NBLK, SCAN_B>>>(cnt, inc, bsum, offs, NN);
    fill_csr_kernel<<<(NE + 255) / 256, 256>>>(ei, ew, dinv, offs, fill, csr_src, csr_nrm, NE);

    // 3) weights: transpose + tf32 round
    wtrans_kernel<<<(INF * HIDF + 255) / 256, 256>>>(W1, w1t, INF, HIDF);
    wtrans_kernel<<<(HIDF * OUTF + 255) / 256, 256>>>(W2, w2t, HIDF, OUTF);

    // 4) y = Â x
    gather_kernel<128, false><<<(NN * 32 + 255) / 256, 256>>>(csr_src, csr_nrm, offs, cnt,
                                                              dinv, x, nullptr, y);
    // 5) z = relu(y@W1+b1)@W2  (fused; h stays in SMEM)
    fused_gemm_kernel<<<(NN + 127) / 128, 256, FUSED_SMEM>>>(y, w1t, b1, w2t, z, NN);

    // 6) out = Â z + b2
    gather_kernel<64, true><<<(NN * 32 + 255) / 256, 256>>>(csr_src, csr_nrm, offs, cnt,
                                                            dinv, z, b2, out);
}

// round 10
// speedup vs baseline: 3.0519x; 1.0094x over previous
#include <cuda_runtime.h>
#include <cuda_bf16.h>
#include <cstdint>

#define NN 100000
#define NE 400000
#define INF 128
#define HIDF 1024
#define OUTF 64
#define SCAN_B 1024
#define NBLK ((NN + SCAN_B - 1) / SCAN_B)

// ---------------- scratch (device globals; no allocation allowed) ----------------
__device__ float g_deg[NN];
__device__ float g_dinv[NN];
__device__ int g_cnt[NN];
__device__ int g_inc[NN];
__device__ int g_bsum[NBLK];
__device__ int g_offs[NN];
__device__ int g_fill[NN];
__device__ int g_csr_src[NE];
__device__ float g_csr_nrm[NE];
__device__ __align__(256) float g_y[(size_t)NN * INF];
__device__ __align__(256) float g_z[(size_t)NN * OUTF];
__device__ __align__(256) float g_w1t[(size_t)HIDF * INF];   // [hid][in] tf32
__device__ __align__(256) float g_w2t[(size_t)OUTF * HIDF];  // [out][hid] tf32

// ---------------- helpers ----------------
__device__ __forceinline__ uint32_t f2tf32(float x) {
    uint32_t r;
    asm("cvt.rna.tf32.f32 %0, %1;" : "=r"(r) : "f"(x));
    return r;
}
__device__ __forceinline__ void mma16n8k8(float* c, const uint32_t* a, const uint32_t* b) {
    asm volatile(
        "mma.sync.aligned.m16n8k8.row.col.f32.tf32.tf32.f32 "
        "{%0,%1,%2,%3}, {%4,%5,%6,%7}, {%8,%9}, {%0,%1,%2,%3};"
        : "+f"(c[0]), "+f"(c[1]), "+f"(c[2]), "+f"(c[3])
        : "r"(a[0]), "r"(a[1]), "r"(a[2]), "r"(a[3]), "r"(b[0]), "r"(b[1]));
}
__device__ __forceinline__ void ldsm_x4(uint32_t* r, uint32_t addr) {
    asm volatile("ldmatrix.sync.aligned.m8n8.x4.shared.b16 {%0,%1,%2,%3}, [%4];"
                 : "=r"(r[0]), "=r"(r[1]), "=r"(r[2]), "=r"(r[3]) : "r"(addr));
}
__device__ __forceinline__ uint32_t smem_u32(const void* p) {
    uint32_t a;
    asm("{ .reg .u64 t; cvta.to.shared.u64 t, %1; cvt.u32.u64 %0, t; }" : "=r"(a) : "l"(p));
    return a;
}
#define CP_ASYNC16(dst, src) \
    asm volatile("cp.async.cg.shared.global [%0], [%1], 16;" :: "r"(dst), "l"(src))
#define CP_COMMIT() asm volatile("cp.async.commit_group;" ::: "memory")
#define CP_WAIT0() asm volatile("cp.async.wait_group 0;" ::: "memory")

// ---------------- graph prep ----------------
__global__ void init_kernel(float* __restrict__ deg, int* __restrict__ cnt,
                            int* __restrict__ fill, int n) {
    int i = blockIdx.x * blockDim.x + threadIdx.x;
    if (i < n) { deg[i] = 1.0f; cnt[i] = 0; fill[i] = 0; }
}
__global__ void accum_kernel(const int* __restrict__ ei, const float* __restrict__ ew,
                             float* __restrict__ deg, int* __restrict__ cnt, int E) {
    int e = blockIdx.x * blockDim.x + threadIdx.x;
    if (e < E) {
        int d = ei[E + e];
        atomicAdd(&deg[d], ew[e]);
        atomicAdd(&cnt[d], 1);
    }
}
__global__ void dinv_kernel(const float* __restrict__ deg, float* __restrict__ dinv, int n) {
    int i = blockIdx.x * blockDim.x + threadIdx.x;
    if (i < n) {
        float d = deg[i];
        dinv[i] = d > 0.0f ? rsqrtf(d) : 0.0f;
    }
}
__global__ void scan_block_kernel(const int* __restrict__ cnt, int* __restrict__ inc,
                                  int* __restrict__ bsum, int n) {
    __shared__ int s[SCAN_B];
    int i = blockIdx.x * SCAN_B + threadIdx.x;
    int v = (i < n) ? cnt[i] : 0;
    s[threadIdx.x] = v;
    __syncthreads();
    for (int d = 1; d < SCAN_B; d <<= 1) {
        int t = (threadIdx.x >= d) ? s[threadIdx.x - d] : 0;
        __syncthreads();
        s[threadIdx.x] += t;
        __syncthreads();
    }
    if (i < n) inc[i] = s[threadIdx.x];
    if (threadIdx.x == SCAN_B - 1) bsum[blockIdx.x] = s[SCAN_B - 1];
}
__global__ void scan_bsum_kernel(int* __restrict__ bsum, int nb) {
    if (threadIdx.x == 0 && blockIdx.x == 0) {
        int acc = 0;
        for (int b = 0; b < nb; b++) { int t = bsum[b]; bsum[b] = acc; acc += t; }
    }
}
__global__ void scan_final_kernel(const int* __restrict__ cnt, const int* __restrict__ inc,
                                  const int* __restrict__ bsum, int* __restrict__ offs, int n) {
    int i = blockIdx.x * SCAN_B + threadIdx.x;
    if (i < n) offs[i] = bsum[blockIdx.x] + inc[i] - cnt[i];
}
__global__ void fill_csr_kernel(const int* __restrict__ ei, const float* __restrict__ ew,
                                const float* __restrict__ dinv, const int* __restrict__ offs,
                                int* __restrict__ fill, int* __restrict__ csr_src,
                                float* __restrict__ csr_nrm, int E) {
    int e = blockIdx.x * blockDim.x + threadIdx.x;
    if (e >= E) return;
    int s = ei[e], d = ei[E + e];
    int pos = offs[d] + atomicAdd(&fill[d], 1);
    csr_src[pos] = s;
    csr_nrm[pos] = dinv[s] * ew[e] * dinv[d];
}

// one warp per dst node
template <int F, bool BIAS>
__global__ void gather_kernel(const int* __restrict__ csr_src, const float* __restrict__ csr_nrm,
                              const int* __restrict__ offs, const int* __restrict__ cnt,
                              const float* __restrict__ dinv, const float* __restrict__ feat,
                              const float* __restrict__ bias, float* __restrict__ out) {
    int warp = (blockIdx.x * blockDim.x + threadIdx.x) >> 5;
    int lane = threadIdx.x & 31;
    if (warp >= NN) return;
    int beg = offs[warp], n = cnt[warp];
    float si = dinv[warp];
    si = si * si;
    if (F == 128) {
        float4 v = reinterpret_cast<const float4*>(feat + (size_t)warp * 128)[lane];
        float4 acc;
        acc.x = si * v.x; acc.y = si * v.y; acc.z = si * v.z; acc.w = si * v.w;
        for (int j = beg; j < beg + n; j++) {
            int s = csr_src[j];
            float nrm = csr_nrm[j];
            float4 f = reinterpret_cast<const float4*>(feat + (size_t)s * 128)[lane];
            acc.x += nrm * f.x; acc.y += nrm * f.y; acc.z += nrm * f.z; acc.w += nrm * f.w;
        }
        reinterpret_cast<float4*>(out + (size_t)warp * 128)[lane] = acc;
    } else {
        float2 v = reinterpret_cast<const float2*>(feat + (size_t)warp * 64)[lane];
        float2 acc;
        acc.x = si * v.x; acc.y = si * v.y;
        for (int j = beg; j < beg + n; j++) {
            int s = csr_src[j];
            float nrm = csr_nrm[j];
            float2 f = reinterpret_cast<const float2*>(feat + (size_t)s * 64)[lane];
            acc.x += nrm * f.x; acc.y += nrm * f.y;
        }
        if (BIAS) {
            float2 b = reinterpret_cast<const float2*>(bias)[lane];
            acc.x += b.x; acc.y += b.y;
        }
        reinterpret_cast<float2*>(out + (size_t)warp * 64)[lane] = acc;
    }
}

// W[K,N] -> Wt[N,K], tf32-rounded
__global__ void wtrans_kernel(const float* __restrict__ W, float* __restrict__ Wt, int K, int N) {
    int idx = blockIdx.x * blockDim.x + threadIdx.x;
    if (idx >= K * N) return;
    int k = idx / N, n = idx - k * N;
    Wt[(size_t)n * K + k] = __uint_as_float(f2tf32(W[idx]));
}

// ---------------- fused 2-layer GEMM (ldmatrix + cp.async double buffer) ----------------
#define AS_STR 132
#define HS_STR 68
#define OFF_AS 0
#define OFF_BS (128 * AS_STR)                       // 2 buffers of [64][132]
#define OFF_HS (OFF_BS + 2 * 64 * AS_STR)
#define OFF_W2 (OFF_HS + 128 * HS_STR)              // 2 buffers of [64][68]
#define FUSED_SMEM ((OFF_W2 + 2 * 64 * HS_STR) * 4)
#define BS_BYTES (64 * AS_STR * 4)
#define W2_BYTES (64 * HS_STR * 4)

__global__ void __launch_bounds__(256) fused_gemm_kernel(
    const float* __restrict__ Y, const float* __restrict__ W1t,
    const float* __restrict__ b1, const float* __restrict__ W2t,
    float* __restrict__ Z, int M) {
    extern __shared__ uint32_t sm[];
    uint32_t* As = sm + OFF_AS;
    uint32_t* Hs = sm + OFF_HS;

    int tid = threadIdx.x, lane = tid & 31, wid = tid >> 5;
    int wm = wid & 3, wn = wid >> 2;
    int m0 = blockIdx.x * 128;

    uint32_t as_u = smem_u32(sm + OFF_AS);
    uint32_t bs_u = smem_u32(sm + OFF_BS);
    uint32_t hs_u = smem_u32(sm + OFF_HS);
    uint32_t w2_u = smem_u32(sm + OFF_W2);

    // ldmatrix lane mapping (x4): lanes 0-7 -> M0 rows, 8-15 -> M1 (+8 rows),
    // 16-23 -> M2 (+4 cols), 24-31 -> M3 (+8 rows, +4 cols)
    int lrow = (((lane >> 3) & 1) << 3) + (lane & 7);
    int lcol = (lane >> 4) << 2;
    int ar = lane >> 2, ac = lane & 3;  // mma fragment coords

    // ---- stage Y tile (tf32) ----
#pragma unroll
    for (int i = 0; i < 16; i++) {
        int u = tid + i * 256;
        int r = u >> 5, c = (u & 31) * 4;
        float4 v;
        if (m0 + r < M)
            v = *reinterpret_cast<const float4*>(Y + (size_t)(m0 + r) * INF + c);
        else
            v = make_float4(0.f, 0.f, 0.f, 0.f);
        uint32_t* p = As + r * AS_STR + c;
        p[0] = f2tf32(v.x); p[1] = f2tf32(v.y); p[2] = f2tf32(v.z); p[3] = f2tf32(v.w);
    }

    // ---- cp.async chunk loader: W1 chunk (64x128) + W2 chunk (64x64) into buf ----
    auto load_chunk = [&](int ch, int buf) {
        int c0 = ch * 64;
        uint32_t bdst = bs_u + buf * BS_BYTES;
#pragma unroll
        for (int i = 0; i < 8; i++) {
            int u = tid + i * 256;          // 0..2047 16B units of W1 chunk
            int r = u >> 5, c = (u & 31) * 4;
            CP_ASYNC16(bdst + (r * AS_STR + c) * 4,
                       W1t + (size_t)(c0 + r) * INF + c);
        }
        uint32_t wdst = w2_u + buf * W2_BYTES;
#pragma unroll
        for (int i = 0; i < 4; i++) {
            int u = tid + i * 256;          // 0..1023 16B units of W2 chunk
            int r = u >> 4, c = (u & 15) * 4;
            CP_ASYNC16(wdst + (r * HS_STR + c) * 4,
                       W2t + (size_t)r * HIDF + c0 + c);
        }
        CP_COMMIT();
    };

    load_chunk(0, 0);

    float acc_out[2][4][4];
#pragma unroll
    for (int mt = 0; mt < 2; mt++)
#pragma unroll
        for (int nt = 0; nt < 4; nt++)
#pragma unroll
            for (int i = 0; i < 4; i++) acc_out[mt][nt][i] = 0.0f;

    for (int ch = 0; ch < HIDF / 64; ch++) {
        int buf = ch & 1;
        CP_WAIT0();
        __syncthreads();  // chunk data visible; prev mma done with alt buffers
        if (ch + 1 < HIDF / 64) load_chunk(ch + 1, buf ^ 1);

        uint32_t bsb = bs_u + buf * BS_BYTES;
        uint32_t w2b = w2_u + buf * W2_BYTES;

        // ---- mma1: h_chunk[128x64] = y_tile @ W1chunk^T, K=128 ----
        float acc_h[2][4][4];
#pragma unroll
        for (int mt = 0; mt < 2; mt++)
#pragma unroll
            for (int nt = 0; nt < 4; nt++)
#pragma unroll
                for (int i = 0; i < 4; i++) acc_h[mt][nt][i] = 0.0f;
#pragma unroll
        for (int kk = 0; kk < 128; kk += 8) {
            uint32_t a[2][4], bp[2][4];
#pragma unroll
            for (int mt = 0; mt < 2; mt++) {
                int rb = wm * 32 + mt * 16;
                ldsm_x4(a[mt], as_u + ((rb + lrow) * AS_STR + kk + lcol) * 4);
            }
#pragma unroll
            for (int np = 0; np < 2; np++) {   // nt pairs (0,1) and (2,3)
                int nb = wn * 32 + np * 16;
                ldsm_x4(bp[np], bsb + ((nb + lrow) * AS_STR + kk + lcol) * 4);
            }
#pragma unroll
            for (int mt = 0; mt < 2; mt++)
#pragma unroll
                for (int np = 0; np < 2; np++) {
                    uint32_t b0[2] = {bp[np][0], bp[np][2]};
                    uint32_t b1r[2] = {bp[np][1], bp[np][3]};
                    mma16n8k8(acc_h[mt][np * 2 + 0], a[mt], b0);
                    mma16n8k8(acc_h[mt][np * 2 + 1], a[mt], b1r);
                }
        }
        // bias + relu -> Hs (tf32)
        int c0 = ch * 64;
#pragma unroll
        for (int mt = 0; mt < 2; mt++) {
#pragma unroll
            for (int half = 0; half < 2; half++) {
                int row = wm * 32 + mt * 16 + ar + half * 8;
#pragma unroll
                for (int nt = 0; nt < 4; nt++) {
                    int col = wn * 32 + nt * 8 + 2 * ac;
                    float bv0 = __ldg(b1 + c0 + col);
                    float bv1 = __ldg(b1 + c0 + col + 1);
                    float v0 = fmaxf(acc_h[mt][nt][half * 2 + 0] + bv0, 0.0f);
                    float v1 = fmaxf(acc_h[mt][nt][half * 2 + 1] + bv1, 0.0f);
                    uint32_t* p = Hs + row * HS_STR + col;
                    p[0] = f2tf32(v0);
                    p[1] = f2tf32(v1);
                }
            }
        }
        __syncthreads();

        // ---- mma2: acc_out += h_chunk @ W2chunk^T, K=64 ----
#pragma unroll
        for (int kk = 0; kk < 64; kk += 8) {
            uint32_t a[2][4], bp[2][4];
#pragma unroll
            for (int mt = 0; mt < 2; mt++) {
                int rb = wm * 32 + mt * 16;
                ldsm_x4(a[mt], hs_u + ((rb + lrow) * HS_STR + kk + lcol) * 4);
            }
#pragma unroll
            for (int np = 0; np < 2; np++) {
                int nb = wn * 32 + np * 16;
                ldsm_x4(bp[np], w2b + ((nb + lrow) * HS_STR + kk + lcol) * 4);
            }
#pragma unroll
            for (int mt = 0; mt < 2; mt++)
#pragma unroll
                for (int np = 0; np < 2; np++) {
                    uint32_t b0[2] = {bp[np][0], bp[np][2]};
                    uint32_t b1r[2] = {bp[np][1], bp[np][3]};
                    mma16n8k8(acc_out[mt][np * 2 + 0], a[mt], b0);
                    mma16n8k8(acc_out[mt][np * 2 + 1], a[mt], b1r);
                }
        }
    }

    // ---- epilogue ----
#pragma unroll
    for (int mt = 0; mt < 2; mt++) {
#pragma unroll
        for (int half = 0; half < 2; half++) {
            int row = m0 + wm * 32 + mt * 16 + ar + half * 8;
            if (row >= M) continue;
#pragma unroll
            for (int nt = 0; nt < 4; nt++) {
                int col = wn * 32 + nt * 8 + 2 * ac;
                *reinterpret_cast<float2*>(Z + (size_t)row * OUTF + col) =
                    make_float2(acc_out[mt][nt][half * 2 + 0], acc_out[mt][nt][half * 2 + 1]);
            }
        }
    }
}

// ---------------- launch ----------------
extern "C" void kernel_launch(void* const* d_in, const int* in_sizes, int n_in,
                              void* d_out, int out_size) {
    const float* x = (const float*)d_in[0];
    const int* ei = (const int*)d_in[1];
    const float* ew = (const float*)d_in[2];
    const float* W1 = (const float*)d_in[3];
    const float* b1 = (const float*)d_in[4];
    const float* W2 = (const float*)d_in[5];
    const float* b2 = (const float*)d_in[6];
    float* out = (float*)d_out;

    float *deg, *dinv, *y, *z, *w1t, *w2t, *csr_nrm;
    int *cnt, *inc, *bsum, *offs, *fill, *csr_src;
    cudaGetSymbolAddress((void**)&deg, g_deg);
    cudaGetSymbolAddress((void**)&dinv, g_dinv);
    cudaGetSymbolAddress((void**)&y, g_y);
    cudaGetSymbolAddress((void**)&z, g_z);
    cudaGetSymbolAddress((void**)&w1t, g_w1t);
    cudaGetSymbolAddress((void**)&w2t, g_w2t);
    cudaGetSymbolAddress((void**)&cnt, g_cnt);
    cudaGetSymbolAddress((void**)&inc, g_inc);
    cudaGetSymbolAddress((void**)&bsum, g_bsum);
    cudaGetSymbolAddress((void**)&offs, g_offs);
    cudaGetSymbolAddress((void**)&fill, g_fill);
    cudaGetSymbolAddress((void**)&csr_src, g_csr_src);
    cudaGetSymbolAddress((void**)&csr_nrm, g_csr_nrm);

    static bool attr_set = false;
    if (!attr_set) {
        cudaFuncSetAttribute(fused_gemm_kernel,
                             cudaFuncAttributeMaxDynamicSharedMemorySize, FUSED_SMEM);
        attr_set = true;
    }

    // 1) degrees + counts + norm
    init_kernel<<<(NN + 255) / 256, 256>>>(deg, cnt, fill, NN);
    accum_kernel<<<(NE + 255) / 256, 256>>>(ei, ew, deg, cnt, NE);
    dinv_kernel<<<(NN + 255) / 256, 256>>>(deg, dinv, NN);

    // 2) CSR build
    scan_block_kernel<<<NBLK, SCAN_B>>>(cnt, inc, bsum, NN);
    scan_bsum_kernel<<<1, 32>>>(bsum, NBLK);
    scan_final_kernel<<<NBLK, SCAN_B>>>(cnt, inc, bsum, offs, NN);
    fill_csr_kernel<<<(NE + 255) / 256, 256>>>(ei, ew, dinv, offs, fill, csr_src, csr_nrm, NE);

    // 3) weights: transpose + tf32 round
    wtrans_kernel<<<(INF * HIDF + 255) / 256, 256>>>(W1, w1t, INF, HIDF);
    wtrans_kernel<<<(HIDF * OUTF + 255) / 256, 256>>>(W2, w2t, HIDF, OUTF);

    // 4) y = Â x
    gather_kernel<128, false><<<(NN * 32 + 255) / 256, 256>>>(csr_src, csr_nrm, offs, cnt,
                                                              dinv, x, nullptr, y);
    // 5) z = relu(y@W1+b1)@W2  (fused; h stays in SMEM)
    fused_gemm_kernel<<<(NN + 127) / 128, 256, FUSED_SMEM>>>(y, w1t, b1, w2t, z, NN);

    // 6) out = Â z + b2
    gather_kernel<64, true><<<(NN * 32 + 255) / 256, 256>>>(csr_src, csr_nrm, offs, cnt,
                                                            dinv, z, b2, out);
}